// round 7
// baseline (speedup 1.0000x reference)
#include <cuda_runtime.h>
#include <stdint.h>

#define ROW_N 2048
#define K_SEL 1024
#define NT    256
#define CAP   8
#define FULLM 0xFFFFFFFFu

__device__ __forceinline__ uint32_t f2u_ord(float x) {
    uint32_t b = __float_as_uint(x);
    uint32_t m = (uint32_t)(((int32_t)b) >> 31) | 0x80000000u;
    return b ^ m;
}

__global__ __launch_bounds__(NT, 8) void kta_kernel(const float* __restrict__ in,
                                                    float* __restrict__ out) {
    __shared__ uint32_t s_hist[256];          // 1 KB
    __shared__ float    s_binv[256 * CAP];    // 8 KB; doubles as flat gather buf (fallback)
    __shared__ uint32_t s_w[8];               // count-below partials
    __shared__ uint32_t s_w2[8];              // scan partials
    __shared__ uint32_t s_sel[3];             // {bin, exclusive count, bin count}
    __shared__ uint32_t s_cnt;
    __shared__ float    s_T;

    const int t    = threadIdx.x;
    const int lane = t & 31;
    const int wid  = t >> 5;
    const size_t base = (size_t)blockIdx.x * ROW_N;
    const float4* in4  = (const float4*)(in  + base);
    float4*       out4 = (float4*)(out + base);

    // ---- load row into registers ----
    float f[8];
    {
        float4 a = in4[t], b4 = in4[t + NT];
        f[0]=a.x;  f[1]=a.y;  f[2]=a.z;  f[3]=a.w;
        f[4]=b4.x; f[5]=b4.y; f[6]=b4.z; f[7]=b4.w;
    }

    int   bsel = 0, rem = 0, bincnt = 0, sel_lvl = 0;
    float sel_scale = 0.f, sel_bias = 0.f;

    for (int lvl = 0; lvl < 3; lvl++) {
        // lvl0: [-0.10, 0.10) scale=1280, bias=128 ; lvl1: [-0.60, 0.60) scale=256/1.2, bias=128
        const float scale = (lvl == 0) ? 1280.0f : (256.0f / 1.2f);
        const float bias  = 128.0f;

        s_hist[t] = 0;
        if (t == 0) s_sel[0] = FULLM;
        __syncthreads();

        // ---- fused histogram + count-below + per-bin value capture ----
        uint32_t myclo = 0;
#pragma unroll
        for (int e = 0; e < 8; e++) {
            int b;
            if (lvl < 2) b = __float2int_rd(fmaf(f[e], scale, bias));
            else         b = (int)(f2u_ord(f[e]) >> 24);
            myclo += ((uint32_t)b >> 31);                 // b < 0
            if ((unsigned)b < 256u) {
                uint32_t pos = atomicAdd(&s_hist[b], 1u);
                if (pos < CAP) s_binv[b * CAP + pos] = f[e];
            }
        }
        myclo = __reduce_add_sync(FULLM, myclo);
        if (lane == 0) s_w[wid] = myclo;
        __syncthreads();

        int clo = 0;
#pragma unroll
        for (int w = 0; w < 8; w++) clo += (int)s_w[w];
        const int k2 = K_SEL - clo;

        // ---- scan 256 bins ----
        uint32_t cnt = s_hist[t];
        uint32_t inc = cnt;
#pragma unroll
        for (int o = 1; o < 32; o <<= 1) {
            uint32_t v = __shfl_up_sync(FULLM, inc, o);
            if (lane >= o) inc += v;
        }
        if (lane == 31) s_w2[wid] = inc;
        __syncthreads();
        uint32_t pre = 0;
#pragma unroll
        for (int w = 0; w < 8; w++) pre += (w < wid) ? s_w2[w] : 0u;  // self-summed fixup
        inc += pre;
        int exc = (int)(inc - cnt);
        if (exc < k2 && k2 <= (int)inc) { s_sel[0] = (uint32_t)t; s_sel[1] = (uint32_t)exc; s_sel[2] = cnt; }
        __syncthreads();

        if (s_sel[0] != FULLM) {
            bsel      = (int)s_sel[0];
            rem       = k2 - (int)s_sel[1];   // 1-based rank within bin
            bincnt    = (int)s_sel[2];
            sel_lvl   = lvl;
            sel_scale = scale;
            sel_bias  = bias;
            break;
        }
        // falls through: next level resets state (barrier at loop top orders reuse)
    }

    // ---- threshold: rank `rem` within the crossing bin ----
    if (bincnt <= CAP) {
        // candidates already captured in s_binv[bsel*CAP ..]
        if (t < bincnt) {
            float v = s_binv[bsel * CAP + t];
            int less = 0, leq = 0;
            for (int j = 0; j < bincnt; j++) {
                float c = s_binv[bsel * CAP + j];
                less += (c <  v) ? 1 : 0;
                leq  += (c <= v) ? 1 : 0;
            }
            if (less < rem && rem <= leq) s_T = v;
        }
    } else {
        // rare overflow fallback: full gather of the crossing bin (CTA-uniform branch)
        if (t == 0) s_cnt = 0;
        __syncthreads();
#pragma unroll
        for (int e = 0; e < 8; e++) {
            int b;
            if (sel_lvl < 2) b = __float2int_rd(fmaf(f[e], sel_scale, sel_bias));
            else             b = (int)(f2u_ord(f[e]) >> 24);
            if (b == bsel) {
                uint32_t pos = atomicAdd(&s_cnt, 1u);
                s_binv[pos] = f[e];               // reuse as flat buffer (cap 2048)
            }
        }
        __syncthreads();
        const int B = (int)s_cnt;
        for (int i = t; i < B; i += NT) {
            float v = s_binv[i];
            int less = 0, leq = 0;
            for (int j = 0; j < B; j++) {
                float c = s_binv[j];
                less += (c <  v) ? 1 : 0;
                leq  += (c <= v) ? 1 : 0;
            }
            if (less < rem && rem <= leq) s_T = v;
        }
    }
    __syncthreads();
    const float T = s_T;

    // ---- output from registers: zero everything <= T ----
    float4 o0, o1;
    o0.x = (f[0] <= T) ? 0.0f : f[0];
    o0.y = (f[1] <= T) ? 0.0f : f[1];
    o0.z = (f[2] <= T) ? 0.0f : f[2];
    o0.w = (f[3] <= T) ? 0.0f : f[3];
    o1.x = (f[4] <= T) ? 0.0f : f[4];
    o1.y = (f[5] <= T) ? 0.0f : f[5];
    o1.z = (f[6] <= T) ? 0.0f : f[6];
    o1.w = (f[7] <= T) ? 0.0f : f[7];
    out4[t]      = o0;
    out4[t + NT] = o1;
}

extern "C" void kernel_launch(void* const* d_in, const int* in_sizes, int n_in,
                              void* d_out, int out_size) {
    const float* in = (const float*)d_in[0];
    float* out = (float*)d_out;
    int rows = in_sizes[0] / ROW_N;
    kta_kernel<<<rows, NT>>>(in, out);
}

// round 8
// speedup vs baseline: 1.0840x; 1.0840x over previous
#include <cuda_runtime.h>
#include <stdint.h>

#define ROW_N 2048
#define K_SEL 1024
#define NT    256
#define FULLM 0xFFFFFFFFu

__device__ __forceinline__ uint32_t f2u_ord(float x) {
    uint32_t b = __float_as_uint(x);
    uint32_t m = (uint32_t)(((int32_t)b) >> 31) | 0x80000000u;
    return b ^ m;
}

__global__ __launch_bounds__(NT, 8) void kta_kernel(const float* __restrict__ in,
                                                    float* __restrict__ out) {
    __shared__ uint32_t s_hist[256];     // 1 KB
    __shared__ float    s_cand[ROW_N];   // 8 KB worst-case gather (degenerate data)
    __shared__ uint32_t s_w[8];          // count-below partials
    __shared__ uint32_t s_sel[2];        // {crossing bin (FULLM=not found), rank-in-bin}
    __shared__ uint32_t s_cnt;
    __shared__ float    s_T;

    const int t    = threadIdx.x;
    const int lane = t & 31;
    const int wid  = t >> 5;
    const size_t base = (size_t)blockIdx.x * ROW_N;
    const float4* in4  = (const float4*)(in  + base);
    float4*       out4 = (float4*)(out + base);

    // ---- load row into registers ----
    float f[8];
    {
        float4 a = in4[t], b4 = in4[t + NT];
        f[0]=a.x;  f[1]=a.y;  f[2]=a.z;  f[3]=a.w;
        f[4]=b4.x; f[5]=b4.y; f[6]=b4.z; f[7]=b4.w;
    }

    int   bsel = 0, rem = 0, sel_lvl = 0;
    float sel_scale = 0.f;

    for (int lvl = 0; lvl < 3; lvl++) {
        // lvl0: [-0.10,0.10) ; lvl1: [-0.60,0.60) ; lvl2: exponent-byte bins (full range)
        const float scale = (lvl == 0) ? 1280.0f : (256.0f / 1.2f);

        s_hist[t] = 0;
        if (t == 0) { s_sel[0] = FULLM; s_cnt = 0; }
        __syncthreads();

        // ---- fused histogram + count-below (fire-and-forget atomics) ----
        uint32_t myclo = 0;
#pragma unroll
        for (int e = 0; e < 8; e++) {
            int b;
            if (lvl < 2) b = __float2int_rd(fmaf(f[e], scale, 128.0f));
            else         b = (int)(f2u_ord(f[e]) >> 24);
            myclo += ((uint32_t)b >> 31);
            if ((unsigned)b < 256u) atomicAdd(&s_hist[b], 1u);
        }
        myclo = __reduce_add_sync(FULLM, myclo);
        if (lane == 0) s_w[wid] = myclo;
        __syncthreads();

        // ---- warp 0: clo + 256-bin scan + crossing-bin locate ----
        if (wid == 0) {
            uint32_t x = (lane < 8) ? s_w[lane] : 0u;
            const int clo = (int)__reduce_add_sync(FULLM, x);
            const int k2  = K_SEL - clo;

            const uint4* h4 = (const uint4*)s_hist;
            uint4 a = h4[lane * 2], b4 = h4[lane * 2 + 1];
            uint32_t c[8] = {a.x, a.y, a.z, a.w, b4.x, b4.y, b4.z, b4.w};
            uint32_t lt = c[0]+c[1]+c[2]+c[3]+c[4]+c[5]+c[6]+c[7];
            uint32_t inc = lt;
#pragma unroll
            for (int o = 1; o < 32; o <<= 1) {
                uint32_t v = __shfl_up_sync(FULLM, inc, o);
                if (lane >= o) inc += v;
            }
            int exc = (int)(inc - lt);
            if (exc < k2 && k2 <= (int)inc) {      // exactly one lane (if any)
                int run = exc, fb = -1;
#pragma unroll
                for (int j = 0; j < 8; j++) {
                    if (fb < 0 && run < k2 && k2 <= run + (int)c[j]) fb = j;
                    else if (fb < 0) run += (int)c[j];
                }
                s_sel[0] = (uint32_t)(lane * 8 + fb);
                s_sel[1] = (uint32_t)(k2 - run);   // 1-based rank within bin
            }
        }
        __syncthreads();

        if (s_sel[0] != FULLM) {
            bsel      = (int)s_sel[0];
            rem       = (int)s_sel[1];
            sel_lvl   = lvl;
            sel_scale = scale;
            break;
        }
        // not found -> next level (loop-top barrier orders s_hist reuse)
    }

    // ---- gather elements of the crossing bin (bit-identical bin math) ----
#pragma unroll
    for (int e = 0; e < 8; e++) {
        int b;
        if (sel_lvl < 2) b = __float2int_rd(fmaf(f[e], sel_scale, 128.0f));
        else             b = (int)(f2u_ord(f[e]) >> 24);
        if (b == bsel) {
            uint32_t pos = atomicAdd(&s_cnt, 1u);
            s_cand[pos] = f[e];
        }
    }
    __syncthreads();
    const int B = (int)s_cnt;

    // ---- exact rank among the B gathered values (B ~ 1 expected) ----
    for (int i = t; i < B; i += NT) {
        float v = s_cand[i];
        int less = 0, leq = 0;
        for (int j = 0; j < B; j++) {
            float c = s_cand[j];
            less += (c <  v) ? 1 : 0;
            leq  += (c <= v) ? 1 : 0;
        }
        if (less < rem && rem <= leq) s_T = v;
    }
    __syncthreads();
    const float T = s_T;

    // ---- output from registers ----
    float4 o0, o1;
    o0.x = (f[0] <= T) ? 0.0f : f[0];
    o0.y = (f[1] <= T) ? 0.0f : f[1];
    o0.z = (f[2] <= T) ? 0.0f : f[2];
    o0.w = (f[3] <= T) ? 0.0f : f[3];
    o1.x = (f[4] <= T) ? 0.0f : f[4];
    o1.y = (f[5] <= T) ? 0.0f : f[5];
    o1.z = (f[6] <= T) ? 0.0f : f[6];
    o1.w = (f[7] <= T) ? 0.0f : f[7];
    out4[t]      = o0;
    out4[t + NT] = o1;
}

extern "C" void kernel_launch(void* const* d_in, const int* in_sizes, int n_in,
                              void* d_out, int out_size) {
    const float* in = (const float*)d_in[0];
    float* out = (float*)d_out;
    int rows = in_sizes[0] / ROW_N;
    kta_kernel<<<rows, NT>>>(in, out);
}

// round 9
// speedup vs baseline: 1.1517x; 1.0625x over previous
#include <cuda_runtime.h>
#include <stdint.h>

#define ROW_N 2048
#define K_SEL 1024
#define NT    256
#define FULLM 0xFFFFFFFFu

__device__ __forceinline__ uint32_t f2u_ord(float x) {
    uint32_t b = __float_as_uint(x);
    uint32_t m = (uint32_t)(((int32_t)b) >> 31) | 0x80000000u;
    return b ^ m;
}

__global__ __launch_bounds__(NT, 6) void kta_kernel(const float* __restrict__ in,
                                                    float* __restrict__ out) {
    __shared__ uint32_t s_hist[512];          // two 256-bin histograms
    __shared__ float    s_cand[2][ROW_N];     // worst-case gather buffers
    __shared__ uint32_t s_w[2][8];            // count-below partials per row
    __shared__ uint32_t s_selbin[2], s_selrem[2];
    __shared__ uint32_t s_cnt[2];
    __shared__ float    s_T[2];

    const int t    = threadIdx.x;
    const int lane = t & 31;
    const int wid  = t >> 5;
    const size_t baseA = (size_t)blockIdx.x * (2 * ROW_N);
    const float4* inA  = (const float4*)(in  + baseA);
    const float4* inB  = (const float4*)(in  + baseA + ROW_N);
    float4*       outA = (float4*)(out + baseA);
    float4*       outB = (float4*)(out + baseA + ROW_N);

    // ---- load both rows: 4 consecutive LDG.128 (front-batched MLP) ----
    float4 a0 = inA[t], a1 = inA[t + NT], b0 = inB[t], b1 = inB[t + NT];
    float fa[8] = {a0.x,a0.y,a0.z,a0.w, a1.x,a1.y,a1.z,a1.w};
    float fb[8] = {b0.x,b0.y,b0.z,b0.w, b1.x,b1.y,b1.z,b1.w};

    bool gotA = false, gotB = false;
    int  lvlA = 0, lvlB = 0;

    for (int lvl = 0; lvl < 3; lvl++) {
        const float scale = (lvl == 0) ? 1280.0f : (256.0f / 1.2f);

        s_hist[t] = 0; s_hist[t + 256] = 0;
        if (t == 0) {
            if (!gotA) s_selbin[0] = FULLM;
            if (!gotB) s_selbin[1] = FULLM;
            s_cnt[0] = 0; s_cnt[1] = 0;
        }
        __syncthreads();

        // ---- fused histogram + count-below, both rows ----
        if (!gotA) {
            uint32_t clo = 0;
#pragma unroll
            for (int e = 0; e < 8; e++) {
                int b = (lvl < 2) ? __float2int_rd(fmaf(fa[e], scale, 128.0f))
                                  : (int)(f2u_ord(fa[e]) >> 24);
                clo += ((uint32_t)b >> 31);
                if ((unsigned)b < 256u) atomicAdd(&s_hist[b], 1u);
            }
            clo = __reduce_add_sync(FULLM, clo);
            if (lane == 0) s_w[0][wid] = clo;
        }
        if (!gotB) {
            uint32_t clo = 0;
#pragma unroll
            for (int e = 0; e < 8; e++) {
                int b = (lvl < 2) ? __float2int_rd(fmaf(fb[e], scale, 128.0f))
                                  : (int)(f2u_ord(fb[e]) >> 24);
                clo += ((uint32_t)b >> 31);
                if ((unsigned)b < 256u) atomicAdd(&s_hist[256 + b], 1u);
            }
            clo = __reduce_add_sync(FULLM, clo);
            if (lane == 0) s_w[1][wid] = clo;
        }
        __syncthreads();

        // ---- warp r (r=0,1): scan row r's 256 bins, locate crossing ----
        if (wid < 2) {
            const int r = wid;
            const bool need = (r == 0) ? !gotA : !gotB;
            if (need) {
                uint32_t x = (lane < 8) ? s_w[r][lane] : 0u;
                const int clo = (int)__reduce_add_sync(FULLM, x);
                const int k2  = K_SEL - clo;

                const uint4* h4 = (const uint4*)(s_hist + r * 256);
                uint4 p = h4[lane * 2], q = h4[lane * 2 + 1];
                uint32_t c[8] = {p.x,p.y,p.z,p.w, q.x,q.y,q.z,q.w};
                uint32_t lt = c[0]+c[1]+c[2]+c[3]+c[4]+c[5]+c[6]+c[7];
                uint32_t inc = lt;
#pragma unroll
                for (int o = 1; o < 32; o <<= 1) {
                    uint32_t v = __shfl_up_sync(FULLM, inc, o);
                    if (lane >= o) inc += v;
                }
                int exc = (int)(inc - lt);
                if (exc < k2 && k2 <= (int)inc) {
                    int run = exc, fbn = -1;
#pragma unroll
                    for (int j = 0; j < 8; j++) {
                        if (fbn < 0 && run < k2 && k2 <= run + (int)c[j]) fbn = j;
                        else if (fbn < 0) run += (int)c[j];
                    }
                    s_selbin[r] = (uint32_t)(lane * 8 + fbn);
                    s_selrem[r] = (uint32_t)(k2 - run);
                }
            }
        }
        __syncthreads();

        bool pA = gotA, pB = gotB;
        gotA = (s_selbin[0] != FULLM);
        gotB = (s_selbin[1] != FULLM);
        if (!pA && gotA) lvlA = lvl;
        if (!pB && gotB) lvlB = lvl;
        if (gotA && gotB) break;
    }

    const int bselA = (int)s_selbin[0], bselB = (int)s_selbin[1];
    const float scA = (lvlA == 0) ? 1280.0f : (256.0f / 1.2f);
    const float scB = (lvlB == 0) ? 1280.0f : (256.0f / 1.2f);

    // ---- gather crossing-bin elements (bit-identical bin math) ----
#pragma unroll
    for (int e = 0; e < 8; e++) {
        int b = (lvlA < 2) ? __float2int_rd(fmaf(fa[e], scA, 128.0f))
                           : (int)(f2u_ord(fa[e]) >> 24);
        if (b == bselA) s_cand[0][atomicAdd(&s_cnt[0], 1u)] = fa[e];
    }
#pragma unroll
    for (int e = 0; e < 8; e++) {
        int b = (lvlB < 2) ? __float2int_rd(fmaf(fb[e], scB, 128.0f))
                           : (int)(f2u_ord(fb[e]) >> 24);
        if (b == bselB) s_cand[1][atomicAdd(&s_cnt[1], 1u)] = fb[e];
    }
    __syncthreads();

    // ---- exact rank within each crossing bin (B ~1 expected) ----
    {
        const int BA = (int)s_cnt[0], remA = (int)s_selrem[0];
        for (int i = t; i < BA; i += NT) {
            float v = s_cand[0][i];
            int less = 0, leq = 0;
            for (int j = 0; j < BA; j++) {
                float c = s_cand[0][j];
                less += (c <  v) ? 1 : 0;
                leq  += (c <= v) ? 1 : 0;
            }
            if (less < remA && remA <= leq) s_T[0] = v;
        }
        const int BB = (int)s_cnt[1], remB = (int)s_selrem[1];
        for (int i = t; i < BB; i += NT) {
            float v = s_cand[1][i];
            int less = 0, leq = 0;
            for (int j = 0; j < BB; j++) {
                float c = s_cand[1][j];
                less += (c <  v) ? 1 : 0;
                leq  += (c <= v) ? 1 : 0;
            }
            if (less < remB && remB <= leq) s_T[1] = v;
        }
    }
    __syncthreads();
    const float TA = s_T[0], TB = s_T[1];

    // ---- output both rows from registers ----
    float4 oa0, oa1, ob0, ob1;
    oa0.x = (fa[0] <= TA) ? 0.0f : fa[0];
    oa0.y = (fa[1] <= TA) ? 0.0f : fa[1];
    oa0.z = (fa[2] <= TA) ? 0.0f : fa[2];
    oa0.w = (fa[3] <= TA) ? 0.0f : fa[3];
    oa1.x = (fa[4] <= TA) ? 0.0f : fa[4];
    oa1.y = (fa[5] <= TA) ? 0.0f : fa[5];
    oa1.z = (fa[6] <= TA) ? 0.0f : fa[6];
    oa1.w = (fa[7] <= TA) ? 0.0f : fa[7];
    ob0.x = (fb[0] <= TB) ? 0.0f : fb[0];
    ob0.y = (fb[1] <= TB) ? 0.0f : fb[1];
    ob0.z = (fb[2] <= TB) ? 0.0f : fb[2];
    ob0.w = (fb[3] <= TB) ? 0.0f : fb[3];
    ob1.x = (fb[4] <= TB) ? 0.0f : fb[4];
    ob1.y = (fb[5] <= TB) ? 0.0f : fb[5];
    ob1.z = (fb[6] <= TB) ? 0.0f : fb[6];
    ob1.w = (fb[7] <= TB) ? 0.0f : fb[7];
    outA[t]      = oa0;
    outA[t + NT] = oa1;
    outB[t]      = ob0;
    outB[t + NT] = ob1;
}

extern "C" void kernel_launch(void* const* d_in, const int* in_sizes, int n_in,
                              void* d_out, int out_size) {
    const float* in = (const float*)d_in[0];
    float* out = (float*)d_out;
    int pairs = in_sizes[0] / (2 * ROW_N);   // 16384
    kta_kernel<<<pairs, NT>>>(in, out);
}